// round 1
// baseline (speedup 1.0000x reference)
#include <cuda_runtime.h>
#include <cstdint>
#include <cstddef>

#define NN 100000
#define EE 1000000
#define DD 64
#define KK 8
#define LL 3

// ---------------- device scratch (no allocation allowed) ----------------
// 6 node-feature buffers: B0,B1,B2 (Chebyshev rotation), B3,B4 (layer outputs), B5=ACC
__device__ float g_bufs[6][(size_t)NN * DD];
__device__ float g_deg[NN];
__device__ float g_dinv[NN];
__device__ float g_norm[EE];

// ---------------- graph normalization ----------------
__global__ void deg_kernel(const int* __restrict__ src, const int* __restrict__ dst,
                           const float* __restrict__ w, float* __restrict__ deg) {
    int e = blockIdx.x * blockDim.x + threadIdx.x;
    if (e >= EE) return;
    int s = src[e];
    float ww = (s == dst[e]) ? 0.0f : w[e];
    if (ww != 0.0f) atomicAdd(&deg[s], ww);
}

__global__ void dinv_kernel(const float* __restrict__ deg, float* __restrict__ dinv) {
    int i = blockIdx.x * blockDim.x + threadIdx.x;
    if (i >= NN) return;
    float d = deg[i];
    dinv[i] = (d > 0.0f) ? rsqrtf(d) : 0.0f;
}

__global__ void norm_kernel(const int* __restrict__ src, const int* __restrict__ dst,
                            const float* __restrict__ w, const float* __restrict__ dinv,
                            float* __restrict__ norm) {
    int e = blockIdx.x * blockDim.x + threadIdx.x;
    if (e >= EE) return;
    int s = src[e], d = dst[e];
    norm[e] = (s == d) ? 0.0f : (-dinv[s] * w[e] * dinv[d]);
}

// ---------------- sparse propagation: out[dst] += norm * h[src] ----------------
// 16 threads per edge, float4 per thread (64 floats/row). Vector atomic scatter.
__global__ void prop_kernel(const float* __restrict__ h, const int* __restrict__ src,
                            const int* __restrict__ dst, const float* __restrict__ norm,
                            float* __restrict__ out) {
    unsigned tid = blockIdx.x * blockDim.x + threadIdx.x;
    unsigned e = tid >> 4;
    unsigned lane = tid & 15u;
    if (e >= EE) return;
    float w = norm[e];
    if (w == 0.0f) return;
    int s = src[e];
    int d = dst[e];
    float4 v = *reinterpret_cast<const float4*>(h + (size_t)s * DD + lane * 4);
    v.x *= w; v.y *= w; v.z *= w; v.w *= w;
    float* p = out + (size_t)d * DD + lane * 4;
    asm volatile("red.global.add.v4.f32 [%0], {%1, %2, %3, %4};"
                 :: "l"(p), "f"(v.x), "f"(v.y), "f"(v.z), "f"(v.w)
                 : "memory");
}

// ---------------- dense GEMM kernels ----------------
// Tile: 128 rows x 64 cols, 256 threads, thread tile 8x4.
// Xs row-major (no transpose needed: a-loads are 2-address broadcasts per warp).

__global__ void gemm_first_kernel(const float* __restrict__ X0, const float* __restrict__ X1,
                                  const float* __restrict__ W,  // W[0]; W[1] = W + 4096
                                  float* __restrict__ acc) {
    __shared__ float Xs[128][DD];
    __shared__ float Ws[DD][DD];
    int tid = threadIdx.x;
    int row0 = blockIdx.x * 128;
    int tx = tid & 15, ty = tid >> 4;

    float accR[8][4];
#pragma unroll
    for (int i = 0; i < 8; i++)
#pragma unroll
        for (int c = 0; c < 4; c++) accR[i][c] = 0.0f;

    for (int pass = 0; pass < 2; ++pass) {
        const float* X = pass ? X1 : X0;
        const float* Wp = W + pass * (DD * DD);
#pragma unroll
        for (int i = 0; i < 4; i++) {
            int f4 = tid + i * 256;
            reinterpret_cast<float4*>(Ws)[f4] = reinterpret_cast<const float4*>(Wp)[f4];
        }
#pragma unroll
        for (int i = 0; i < 8; i++) {
            int f4 = tid + i * 256;        // over 128 rows x 16 float4
            int r = f4 >> 4, c4 = f4 & 15;
            int gr = row0 + r;
            float4 v = make_float4(0.f, 0.f, 0.f, 0.f);
            if (gr < NN) v = reinterpret_cast<const float4*>(X + (size_t)gr * DD)[c4];
            reinterpret_cast<float4*>(&Xs[r][0])[c4] = v;
        }
        __syncthreads();
#pragma unroll 8
        for (int j = 0; j < DD; j++) {
            float4 b = reinterpret_cast<float4*>(&Ws[j][0])[tx];
            float a[8];
#pragma unroll
            for (int i = 0; i < 8; i++) a[i] = Xs[ty * 8 + i][j];
#pragma unroll
            for (int i = 0; i < 8; i++) {
                accR[i][0] += a[i] * b.x;
                accR[i][1] += a[i] * b.y;
                accR[i][2] += a[i] * b.z;
                accR[i][3] += a[i] * b.w;
            }
        }
        __syncthreads();
    }
#pragma unroll
    for (int i = 0; i < 8; i++) {
        int gr = row0 + ty * 8 + i;
        if (gr < NN) {
            float4 v = make_float4(accR[i][0], accR[i][1], accR[i][2], accR[i][3]);
            reinterpret_cast<float4*>(acc + (size_t)gr * DD)[tx] = v;
        }
    }
}

// Fused Chebyshev step: T2 = 2*P - T0 (written back to P in place), acc += T2 @ W
__global__ void gemm_step_kernel(float* __restrict__ P, const float* __restrict__ T0,
                                 const float* __restrict__ W, float* __restrict__ acc) {
    __shared__ float Xs[128][DD];
    __shared__ float Ws[DD][DD];
    int tid = threadIdx.x;
    int row0 = blockIdx.x * 128;
    int tx = tid & 15, ty = tid >> 4;

#pragma unroll
    for (int i = 0; i < 4; i++) {
        int f4 = tid + i * 256;
        reinterpret_cast<float4*>(Ws)[f4] = reinterpret_cast<const float4*>(W)[f4];
    }
#pragma unroll
    for (int i = 0; i < 8; i++) {
        int f4 = tid + i * 256;
        int r = f4 >> 4, c4 = f4 & 15;
        int gr = row0 + r;
        float4 v = make_float4(0.f, 0.f, 0.f, 0.f);
        if (gr < NN) {
            float4 p = reinterpret_cast<const float4*>(P + (size_t)gr * DD)[c4];
            float4 t = reinterpret_cast<const float4*>(T0 + (size_t)gr * DD)[c4];
            v.x = 2.0f * p.x - t.x;
            v.y = 2.0f * p.y - t.y;
            v.z = 2.0f * p.z - t.z;
            v.w = 2.0f * p.w - t.w;
            reinterpret_cast<float4*>(P + (size_t)gr * DD)[c4] = v;  // T2 for next iter
        }
        reinterpret_cast<float4*>(&Xs[r][0])[c4] = v;
    }
    __syncthreads();

    float accR[8][4];
#pragma unroll
    for (int i = 0; i < 8; i++)
#pragma unroll
        for (int c = 0; c < 4; c++) accR[i][c] = 0.0f;

#pragma unroll 8
    for (int j = 0; j < DD; j++) {
        float4 b = reinterpret_cast<float4*>(&Ws[j][0])[tx];
        float a[8];
#pragma unroll
        for (int i = 0; i < 8; i++) a[i] = Xs[ty * 8 + i][j];
#pragma unroll
        for (int i = 0; i < 8; i++) {
            accR[i][0] += a[i] * b.x;
            accR[i][1] += a[i] * b.y;
            accR[i][2] += a[i] * b.z;
            accR[i][3] += a[i] * b.w;
        }
    }

#pragma unroll
    for (int i = 0; i < 8; i++) {
        int gr = row0 + ty * 8 + i;
        if (gr < NN) {
            float4* ap = reinterpret_cast<float4*>(acc + (size_t)gr * DD) + tx;
            float4 old = *ap;
            old.x += accR[i][0];
            old.y += accR[i][1];
            old.z += accR[i][2];
            old.w += accR[i][3];
            *ap = old;
        }
    }
}

// out = relu(acc + bias)
__global__ void relu_bias_kernel(const float* __restrict__ acc, const float* __restrict__ bias,
                                 float* __restrict__ out) {
    unsigned i4 = blockIdx.x * blockDim.x + threadIdx.x;   // float4 index over NN*16
    if (i4 >= (unsigned)(NN * (DD / 4))) return;
    float4 a = reinterpret_cast<const float4*>(acc)[i4];
    float4 b = reinterpret_cast<const float4*>(bias)[i4 & 15u];
    float4 r;
    r.x = fmaxf(a.x + b.x, 0.f);
    r.y = fmaxf(a.y + b.y, 0.f);
    r.z = fmaxf(a.z + b.z, 0.f);
    r.w = fmaxf(a.w + b.w, 0.f);
    reinterpret_cast<float4*>(out)[i4] = r;
}

// ---------------- launcher ----------------
extern "C" void kernel_launch(void* const* d_in, const int* in_sizes, int n_in,
                              void* d_out, int out_size) {
    const float* x  = (const float*)d_in[0];   // [N, 64]
    const int*   ei = (const int*)d_in[1];     // [2, E]
    const float* ew = (const float*)d_in[2];   // [E]
    const float* Wt = (const float*)d_in[3];   // [L, K, 64, 64]
    const float* Bs = (const float*)d_in[4];   // [L, 64]
    const int* src = ei;
    const int* dst = ei + EE;

    float *bufs, *deg, *dinv, *nrm;
    cudaGetSymbolAddress((void**)&bufs, g_bufs);
    cudaGetSymbolAddress((void**)&deg, g_deg);
    cudaGetSymbolAddress((void**)&dinv, g_dinv);
    cudaGetSymbolAddress((void**)&nrm, g_norm);

    const size_t FB = (size_t)NN * DD;
    float* B[6];
    for (int i = 0; i < 6; i++) B[i] = bufs + i * FB;
    float* ACC = B[5];

    const int T = 256;
    const int edgeBlocks = (EE + T - 1) / T;
    const int propBlocks = (EE * 16 + T - 1) / T;
    const int nodeBlocks = (NN + T - 1) / T;
    const int gemmBlocks = (NN + 127) / 128;
    const int reluBlocks = (NN * (DD / 4) + T - 1) / T;

    // normalization (recomputed each call: must be deterministic & stateless)
    cudaMemsetAsync(deg, 0, NN * sizeof(float));
    deg_kernel<<<edgeBlocks, T>>>(src, dst, ew, deg);
    dinv_kernel<<<nodeBlocks, T>>>(deg, dinv);
    norm_kernel<<<edgeBlocks, T>>>(src, dst, ew, dinv, nrm);

    const float* hin = x;
    float* houts[3] = {B[3], B[4], (float*)d_out};
    static const int order[6] = {1, 2, 0, 1, 2, 0};

    for (int l = 0; l < LL; l++) {
        const float* Wl = Wt + (size_t)l * KK * DD * DD;
        // T1 = L_hat @ hin
        cudaMemsetAsync(B[0], 0, FB * sizeof(float));
        prop_kernel<<<propBlocks, T>>>(hin, src, dst, nrm, B[0]);
        // acc = hin@W0 + T1@W1
        gemm_first_kernel<<<gemmBlocks, T>>>(hin, B[0], Wl, ACC);

        const float* t0 = hin;
        float* t1 = B[0];
        for (int k = 2; k < KK; k++) {
            float* pb = B[order[k - 2]];
            cudaMemsetAsync(pb, 0, FB * sizeof(float));
            prop_kernel<<<propBlocks, T>>>(t1, src, dst, nrm, pb);
            // pb = 2*pb - t0; acc += pb @ W[k]
            gemm_step_kernel<<<gemmBlocks, T>>>(pb, t0, Wl + (size_t)k * DD * DD, ACC);
            t0 = t1;
            t1 = pb;
        }
        relu_bias_kernel<<<reluBlocks, T>>>(ACC, Bs + (size_t)l * DD, houts[l]);
        hin = houts[l];
    }
}

// round 2
// speedup vs baseline: 1.8170x; 1.8170x over previous
#include <cuda_runtime.h>
#include <cstdint>
#include <cstddef>

#define NN 100000
#define EE 1000000
#define DD 64
#define KK 8
#define LL 3

#define SCAN_TPB 1024
#define SCAN_BLOCKS ((NN + SCAN_TPB - 1) / SCAN_TPB)   // 98

// ---------------- device scratch (statically allocated; no runtime alloc) ----------------
// 7 Chebyshev buffers T1..T7 + 2 layer-output buffers
__device__ float g_T[7][(size_t)NN * DD];
__device__ float g_out1[(size_t)NN * DD];
__device__ float g_out2[(size_t)NN * DD];
__device__ float g_deg[NN];
__device__ float g_dinv[NN];
__device__ int   g_cnt[NN];        // histogram, then scatter cursor
__device__ int   g_rowstart[NN + 1];
__device__ int   g_cursor[NN];
__device__ int   g_bsum[SCAN_BLOCKS + 32];
__device__ float2 g_adj[EE];       // packed (src_as_float_bits, norm)

// ---------------- normalization + CSR build ----------------
__global__ void deg_hist_kernel(const int* __restrict__ src, const int* __restrict__ dst,
                                const float* __restrict__ w,
                                float* __restrict__ deg, int* __restrict__ cnt) {
    int e = blockIdx.x * blockDim.x + threadIdx.x;
    if (e >= EE) return;
    int s = src[e], d = dst[e];
    float ww = (s == d) ? 0.0f : w[e];
    if (ww != 0.0f) atomicAdd(&deg[s], ww);
    atomicAdd(&cnt[d], 1);
}

__global__ void dinv_kernel(const float* __restrict__ deg, float* __restrict__ dinv) {
    int i = blockIdx.x * blockDim.x + threadIdx.x;
    if (i >= NN) return;
    float d = deg[i];
    dinv[i] = (d > 0.0f) ? rsqrtf(d) : 0.0f;
}

// Block-level exclusive scan of cnt -> rowstart, block sums -> bsum
__global__ void scan_block_kernel(const int* __restrict__ cnt, int* __restrict__ rowstart,
                                  int* __restrict__ bsum) {
    __shared__ int s[SCAN_TPB];
    int i = blockIdx.x * SCAN_TPB + threadIdx.x;
    int v = (i < NN) ? cnt[i] : 0;
    s[threadIdx.x] = v;
    __syncthreads();
#pragma unroll
    for (int off = 1; off < SCAN_TPB; off <<= 1) {
        int t = (threadIdx.x >= off) ? s[threadIdx.x - off] : 0;
        __syncthreads();
        s[threadIdx.x] += t;
        __syncthreads();
    }
    if (i < NN) rowstart[i] = s[threadIdx.x] - v;   // exclusive
    if (threadIdx.x == SCAN_TPB - 1) bsum[blockIdx.x] = s[threadIdx.x];
}

__global__ void scan_sums_kernel(int* __restrict__ bsum) {
    __shared__ int s[128];
    int t = threadIdx.x;
    int v = (t < SCAN_BLOCKS) ? bsum[t] : 0;
    s[t] = v;
    __syncthreads();
#pragma unroll
    for (int off = 1; off < 128; off <<= 1) {
        int tt = (t >= off) ? s[t - off] : 0;
        __syncthreads();
        s[t] += tt;
        __syncthreads();
    }
    if (t < SCAN_BLOCKS) bsum[t] = s[t] - v;        // exclusive block offsets
}

__global__ void scan_add_kernel(int* __restrict__ rowstart, const int* __restrict__ bsum,
                                int* __restrict__ cursor) {
    int i = blockIdx.x * blockDim.x + threadIdx.x;
    if (i == 0) rowstart[NN] = EE;
    if (i >= NN) return;
    int r = rowstart[i] + bsum[i / SCAN_TPB];
    rowstart[i] = r;
    cursor[i] = r;
}

// Scatter edges into CSR-by-dst; norm computed inline.
__global__ void scatter_kernel(const int* __restrict__ src, const int* __restrict__ dst,
                               const float* __restrict__ w, const float* __restrict__ dinv,
                               int* __restrict__ cursor, float2* __restrict__ adj) {
    int e = blockIdx.x * blockDim.x + threadIdx.x;
    if (e >= EE) return;
    int s = src[e], d = dst[e];
    float ww = (s == d) ? 0.0f : w[e];
    float nrm = -dinv[s] * ww * dinv[d];
    int pos = atomicAdd(&cursor[d], 1);
    adj[pos] = make_float2(__int_as_float(s), nrm);
}

// ---------------- CSR gather propagation ----------------
// 16 threads per node, float4 per lane. FIRST: out = L_hat h. Else: out = 2*L_hat h - t0.
template <bool FIRST>
__global__ void prop_csr_kernel(const float* __restrict__ h, const float2* __restrict__ adj,
                                const int* __restrict__ rowstart, const float* __restrict__ t0,
                                float* __restrict__ out) {
    unsigned tid = blockIdx.x * blockDim.x + threadIdx.x;
    unsigned n = tid >> 4;
    if (n >= NN) return;
    unsigned lane = tid & 15u;
    int r0 = rowstart[n];
    int r1 = rowstart[n + 1];
    float4 acc = make_float4(0.f, 0.f, 0.f, 0.f);
    int e = r0;
    for (; e + 1 < r1; e += 2) {
        float2 p0 = __ldg(&adj[e]);
        float2 p1 = __ldg(&adj[e + 1]);
        int s0 = __float_as_int(p0.x);
        int s1 = __float_as_int(p1.x);
        float4 v0 = *reinterpret_cast<const float4*>(h + (size_t)s0 * DD + lane * 4);
        float4 v1 = *reinterpret_cast<const float4*>(h + (size_t)s1 * DD + lane * 4);
        acc.x = fmaf(p0.y, v0.x, acc.x); acc.y = fmaf(p0.y, v0.y, acc.y);
        acc.z = fmaf(p0.y, v0.z, acc.z); acc.w = fmaf(p0.y, v0.w, acc.w);
        acc.x = fmaf(p1.y, v1.x, acc.x); acc.y = fmaf(p1.y, v1.y, acc.y);
        acc.z = fmaf(p1.y, v1.z, acc.z); acc.w = fmaf(p1.y, v1.w, acc.w);
    }
    if (e < r1) {
        float2 p0 = __ldg(&adj[e]);
        int s0 = __float_as_int(p0.x);
        float4 v0 = *reinterpret_cast<const float4*>(h + (size_t)s0 * DD + lane * 4);
        acc.x = fmaf(p0.y, v0.x, acc.x); acc.y = fmaf(p0.y, v0.y, acc.y);
        acc.z = fmaf(p0.y, v0.z, acc.z); acc.w = fmaf(p0.y, v0.w, acc.w);
    }
    float* op = out + (size_t)n * DD + lane * 4;
    if (FIRST) {
        *reinterpret_cast<float4*>(op) = acc;
    } else {
        float4 t = *reinterpret_cast<const float4*>(t0 + (size_t)n * DD + lane * 4);
        float4 r;
        r.x = 2.0f * acc.x - t.x;
        r.y = 2.0f * acc.y - t.y;
        r.z = 2.0f * acc.z - t.z;
        r.w = 2.0f * acc.w - t.w;
        *reinterpret_cast<float4*>(op) = r;
    }
}

// ---------------- fused 8-way GEMM + bias + relu ----------------
struct TPtrs { const float* p[KK]; };

__global__ void gemm8_kernel(TPtrs ts, const float* __restrict__ W /* [8,64,64] */,
                             const float* __restrict__ bias, float* __restrict__ out) {
    __shared__ float Xs[128][DD];
    __shared__ float Ws[DD][DD];
    int tid = threadIdx.x;
    int row0 = blockIdx.x * 128;
    int tx = tid & 15, ty = tid >> 4;

    float accR[8][4];
#pragma unroll
    for (int i = 0; i < 8; i++)
#pragma unroll
        for (int c = 0; c < 4; c++) accR[i][c] = 0.0f;

    for (int k = 0; k < KK; ++k) {
        const float* X = ts.p[k];
        const float* Wp = W + (size_t)k * DD * DD;
#pragma unroll
        for (int i = 0; i < 4; i++) {
            int f4 = tid + i * 256;
            reinterpret_cast<float4*>(Ws)[f4] = reinterpret_cast<const float4*>(Wp)[f4];
        }
#pragma unroll
        for (int i = 0; i < 8; i++) {
            int f4 = tid + i * 256;        // 128 rows x 16 float4
            int r = f4 >> 4, c4 = f4 & 15;
            int gr = row0 + r;
            float4 v = make_float4(0.f, 0.f, 0.f, 0.f);
            if (gr < NN) v = reinterpret_cast<const float4*>(X + (size_t)gr * DD)[c4];
            reinterpret_cast<float4*>(&Xs[r][0])[c4] = v;
        }
        __syncthreads();
#pragma unroll 8
        for (int j = 0; j < DD; j++) {
            float4 b = reinterpret_cast<float4*>(&Ws[j][0])[tx];
            float a[8];
#pragma unroll
            for (int i = 0; i < 8; i++) a[i] = Xs[ty * 8 + i][j];
#pragma unroll
            for (int i = 0; i < 8; i++) {
                accR[i][0] = fmaf(a[i], b.x, accR[i][0]);
                accR[i][1] = fmaf(a[i], b.y, accR[i][1]);
                accR[i][2] = fmaf(a[i], b.z, accR[i][2]);
                accR[i][3] = fmaf(a[i], b.w, accR[i][3]);
            }
        }
        __syncthreads();
    }

    float4 b4 = reinterpret_cast<const float4*>(bias)[tx];
#pragma unroll
    for (int i = 0; i < 8; i++) {
        int gr = row0 + ty * 8 + i;
        if (gr < NN) {
            float4 v;
            v.x = fmaxf(accR[i][0] + b4.x, 0.f);
            v.y = fmaxf(accR[i][1] + b4.y, 0.f);
            v.z = fmaxf(accR[i][2] + b4.z, 0.f);
            v.w = fmaxf(accR[i][3] + b4.w, 0.f);
            reinterpret_cast<float4*>(out + (size_t)gr * DD)[tx] = v;
        }
    }
}

// ---------------- launcher ----------------
extern "C" void kernel_launch(void* const* d_in, const int* in_sizes, int n_in,
                              void* d_out, int out_size) {
    const float* x  = (const float*)d_in[0];   // [N, 64]
    const int*   ei = (const int*)d_in[1];     // [2, E]
    const float* ew = (const float*)d_in[2];   // [E]
    const float* Wt = (const float*)d_in[3];   // [L, K, 64, 64]
    const float* Bs = (const float*)d_in[4];   // [L, 64]
    const int* src = ei;
    const int* dst = ei + EE;

    float *Tbuf, *out1, *out2, *deg, *dinv;
    int *cnt, *rowstart, *cursor, *bsum;
    float2* adj;
    cudaGetSymbolAddress((void**)&Tbuf, g_T);
    cudaGetSymbolAddress((void**)&out1, g_out1);
    cudaGetSymbolAddress((void**)&out2, g_out2);
    cudaGetSymbolAddress((void**)&deg, g_deg);
    cudaGetSymbolAddress((void**)&dinv, g_dinv);
    cudaGetSymbolAddress((void**)&cnt, g_cnt);
    cudaGetSymbolAddress((void**)&rowstart, g_rowstart);
    cudaGetSymbolAddress((void**)&cursor, g_cursor);
    cudaGetSymbolAddress((void**)&bsum, g_bsum);
    cudaGetSymbolAddress((void**)&adj, g_adj);

    const size_t FB = (size_t)NN * DD;
    float* TB[7];
    for (int i = 0; i < 7; i++) TB[i] = Tbuf + (size_t)i * FB;

    const int T = 256;
    const int edgeBlocks = (EE + T - 1) / T;
    const int nodeBlocks = (NN + T - 1) / T;
    const int propBlocks = (NN * 16 + T - 1) / T;
    const int gemmBlocks = (NN + 127) / 128;

    // --- normalization + CSR build (stateless each call) ---
    cudaMemsetAsync(deg, 0, NN * sizeof(float));
    cudaMemsetAsync(cnt, 0, NN * sizeof(int));
    deg_hist_kernel<<<edgeBlocks, T>>>(src, dst, ew, deg, cnt);
    dinv_kernel<<<nodeBlocks, T>>>(deg, dinv);
    scan_block_kernel<<<SCAN_BLOCKS, SCAN_TPB>>>(cnt, rowstart, bsum);
    scan_sums_kernel<<<1, 128>>>(bsum);
    scan_add_kernel<<<nodeBlocks, T>>>(rowstart, bsum, cursor);
    scatter_kernel<<<edgeBlocks, T>>>(src, dst, ew, dinv, cursor, adj);

    // --- layers ---
    const float* hin = x;
    float* houts[3] = {out1, out2, (float*)d_out};

    for (int l = 0; l < LL; l++) {
        const float* Wl = Wt + (size_t)l * KK * DD * DD;
        // T1 = L_hat @ T0
        prop_csr_kernel<true><<<propBlocks, T>>>(hin, adj, rowstart, nullptr, TB[0]);
        // Tk = 2 L_hat T(k-1) - T(k-2), k = 2..7
        for (int k = 2; k < KK; k++) {
            const float* tin = TB[k - 2];
            const float* t0 = (k == 2) ? hin : TB[k - 3];
            prop_csr_kernel<false><<<propBlocks, T>>>(tin, adj, rowstart, t0, TB[k - 1]);
        }
        // out = relu(sum_k Tk @ Wk + b)
        TPtrs ts;
        ts.p[0] = hin;
        for (int k = 1; k < KK; k++) ts.p[k] = TB[k - 1];
        gemm8_kernel<<<gemmBlocks, T>>>(ts, Wl, Bs + (size_t)l * DD, houts[l]);
        hin = houts[l];
    }
}